// round 6
// baseline (speedup 1.0000x reference)
#include <cuda_runtime.h>

// out[i] = { cos(x0), cos(x0)cos(x1), cos(x0)cos(x1)cos(x2), cos(x0)..cos(x3) }
// (circuit collapses analytically; weights are irrelevant — see R1 derivation)
//
// R5: balance fix — 128-thread blocks, grid=2048 (13-14 blocks/SM, single wave,
// ~7% imbalance vs ~14% at grid=1024). VPT=2 front-batched, MUFU __cosf.

constexpr int VPT = 2;          // rows (float4) per thread
constexpr int THREADS = 128;

__global__ __launch_bounds__(THREADS) void qlg_kernel(const float4* __restrict__ x,
                                                      float4* __restrict__ out) {
    int base = blockIdx.x * (THREADS * VPT) + threadIdx.x;

    float4 v[VPT];
#pragma unroll
    for (int j = 0; j < VPT; j++) {
        v[j] = x[base + j * THREADS];       // front-batched, coalesced
    }

#pragma unroll
    for (int j = 0; j < VPT; j++) {
        float c0 = __cosf(v[j].x);
        float c1 = c0 * __cosf(v[j].y);
        float c2 = c1 * __cosf(v[j].z);
        float c3 = c2 * __cosf(v[j].w);
        out[base + j * THREADS] = make_float4(c0, c1, c2, c3);
    }
}

extern "C" void kernel_launch(void* const* d_in, const int* in_sizes, int n_in,
                              void* d_out, int out_size) {
    const float4* x = (const float4*)d_in[0];   // [B,4] float32
    float4* out = (float4*)d_out;               // [B,4] float32
    int n_rows = in_sizes[0] / 4;               // B = 524288 (divisible by 256)
    int blocks = n_rows / (THREADS * VPT);      // 2048 — single wave, fine-grained
    qlg_kernel<<<blocks, THREADS>>>(x, out);
}

// round 10
// speedup vs baseline: 1.1256x; 1.1256x over previous
#include <cuda_runtime.h>

// out[i] = { cos(x0), cos(x0)cos(x1), cos(x0)cos(x1)cos(x2), cos(x0)..cos(x3) }
// (circuit collapses analytically; weights are irrelevant — see R1 derivation)
//
// R8: re-run of R6 (previous round was an infra failure, no measurement).
// VPT=1 max-parallelism shape (524288 threads, one LDG.128 per thread issued
// immediately) WITH cheap MUFU __cosf — decouples R1's shape-vs-math confound.

constexpr int THREADS = 256;

__global__ __launch_bounds__(THREADS) void qlg_kernel(const float4* __restrict__ x,
                                                      float4* __restrict__ out) {
    int i = blockIdx.x * THREADS + threadIdx.x;
    float4 v = x[i];
    float c0 = __cosf(v.x);
    float c1 = c0 * __cosf(v.y);
    float c2 = c1 * __cosf(v.z);
    float c3 = c2 * __cosf(v.w);
    out[i] = make_float4(c0, c1, c2, c3);
}

extern "C" void kernel_launch(void* const* d_in, const int* in_sizes, int n_in,
                              void* d_out, int out_size) {
    const float4* x = (const float4*)d_in[0];   // [B,4] float32
    float4* out = (float4*)d_out;               // [B,4] float32
    int n_rows = in_sizes[0] / 4;               // B = 524288 (divisible by 256)
    int blocks = n_rows / THREADS;              // 2048
    qlg_kernel<<<blocks, THREADS>>>(x, out);
}